// round 1
// baseline (speedup 1.0000x reference)
#include <cuda_runtime.h>
#include <math.h>

#define BATCH 32
#define HDIM 32
#define WDIM 32
#define CH 128
#define NTOT (BATCH*HDIM*WDIM*CH)   // 4194304
#define NPIX (BATCH*HDIM*WDIM)      // 32768
#define NQ (NTOT/4)
#define ERR_BLOCKS 1024
#define EW_BLOCKS 512
#define MAX_STEPS 32
#define WSIZE (3*3*129*128)         // 148608

// ---- Dormand-Prince coefficients (double-folded to f32, matching jnp) ----
#define C10 0.2f
#define C20 ((float)(3.0/40.0))
#define C21 ((float)(9.0/40.0))
#define C30 ((float)(44.0/45.0))
#define C31 ((float)(-56.0/15.0))
#define C32 ((float)(32.0/9.0))
#define C40 ((float)(19372.0/6561.0))
#define C41 ((float)(-25360.0/2187.0))
#define C42 ((float)(64448.0/6561.0))
#define C43 ((float)(-212.0/729.0))
#define C50 ((float)(9017.0/3168.0))
#define C51 ((float)(-355.0/33.0))
#define C52 ((float)(46732.0/5247.0))
#define C53 ((float)(49.0/176.0))
#define C54 ((float)(-5103.0/18656.0))
#define B0c ((float)(35.0/384.0))
#define B2c ((float)(500.0/1113.0))
#define B3c ((float)(125.0/192.0))
#define B4c ((float)(-2187.0/6784.0))
#define B5c ((float)(11.0/84.0))
#define E0c ((float)(35.0/384.0 - 5179.0/57600.0))
#define E2c ((float)(500.0/1113.0 - 7571.0/16695.0))
#define E3c ((float)(125.0/192.0 - 393.0/640.0))
#define E4c ((float)(-2187.0/6784.0 + 92097.0/339200.0))
#define E5c ((float)(11.0/84.0 - 187.0/2100.0))
#define E6c ((float)(-1.0/40.0))

// ---- Persistent state (static __device__ arrays; no allocations) ----
__device__ __align__(16) float g_y[NTOT];
__device__ __align__(16) float g_tmp[NTOT];
__device__ __align__(16) float g_h[NTOT];
__device__ __align__(16) float g_y5[NTOT];
__device__ __align__(16) float g_k[7][NTOT];
__device__ double g_part[ERR_BLOCKS];
__device__ float g_t, g_dt, g_dtc, g_ts7[7];
__device__ int g_done, g_adv;

// ---- init: copy x -> y, reset scalars ----
__global__ void k_init(const float* __restrict__ x){
    int i = blockIdx.x*blockDim.x + threadIdx.x;
    if (i == 0){ g_t=0.f; g_dt=0.05f; g_dtc=0.05f; g_done=0; g_adv=0; }
    const float4* xs=(const float4*)x; float4* ys=(float4*)g_y;
    int st = gridDim.x*blockDim.x;
    for (int q=i; q<NQ; q+=st) ys[q]=xs[q];
}

// ---- begin iteration: dt_c and stage times ----
__global__ void k_ctl_begin(){
    if (g_done) return;
    float t=g_t, dt=g_dt;
    float dtc = fminf(dt, 1.0f - t);
    g_dtc = dtc;
    g_ts7[0]=t;
    g_ts7[1]=t+0.2f*dtc;
    g_ts7[2]=t+0.3f*dtc;
    g_ts7[3]=t+0.8f*dtc;
    g_ts7[4]=t+((float)(8.0/9.0))*dtc;
    g_ts7[5]=t+dtc;
    g_ts7[6]=t+dtc;
}

// ---- stage combine: ytmp = y + dtc * sum(a_j k_j); s==6 writes y5 ----
__global__ void k_combine(int s){
    if (g_done) return;
    const float dtc = g_dtc;
    int i0 = blockIdx.x*blockDim.x+threadIdx.x;
    int stride = gridDim.x*blockDim.x;
    if (s==1){
        for (int i=i0;i<NTOT;i+=stride)
            g_tmp[i] = g_y[i] + dtc*(C10*g_k[0][i]);
    } else if (s==2){
        for (int i=i0;i<NTOT;i+=stride)
            g_tmp[i] = g_y[i] + dtc*(C20*g_k[0][i] + C21*g_k[1][i]);
    } else if (s==3){
        for (int i=i0;i<NTOT;i+=stride)
            g_tmp[i] = g_y[i] + dtc*(C30*g_k[0][i] + C31*g_k[1][i] + C32*g_k[2][i]);
    } else if (s==4){
        for (int i=i0;i<NTOT;i+=stride)
            g_tmp[i] = g_y[i] + dtc*(C40*g_k[0][i] + C41*g_k[1][i] + C42*g_k[2][i] + C43*g_k[3][i]);
    } else if (s==5){
        for (int i=i0;i<NTOT;i+=stride)
            g_tmp[i] = g_y[i] + dtc*(C50*g_k[0][i] + C51*g_k[1][i] + C52*g_k[2][i]
                                   + C53*g_k[3][i] + C54*g_k[4][i]);
    } else { // s==6 -> y5 (5th-order solution)
        for (int i=i0;i<NTOT;i+=stride)
            g_y5[i] = g_y[i] + dtc*(B0c*g_k[0][i] + B2c*g_k[2][i] + B3c*g_k[3][i]
                                  + B4c*g_k[4][i] + B5c*g_k[5][i]);
    }
}

// ---- conv 3x3 SAME, 129 in-ch (ch128 == t constant, zero-padded), 128 out-ch, +bias, relu ----
// Implicit GEMM: per tap, C[128pix x 128co] += A[128pix x 128ci] * W[128ci x 128co].
// t-channel folded into epilogue with per-pixel tap-validity masks.
__global__ __launch_bounds__(256, 2)
void k_conv(const float* __restrict__ Wt, const float* __restrict__ Bias,
            int s, int in_sel, int out_sel)
{
    if (g_done) return;
    const float* __restrict__ X =
        (in_sel==0) ? (const float*)g_y :
        (in_sel==1) ? (const float*)g_tmp :
        (in_sel==2) ? (const float*)g_y5 : (const float*)g_h;
    float* __restrict__ Out = (out_sel < 0) ? (float*)g_h : (float*)g_k[out_sel];
    const float tval = g_ts7[s];

    __shared__ __align__(16) float As[16][128];
    __shared__ __align__(16) float Bs[16][128];

    const int tid = threadIdx.x;
    const int tmg = tid >> 4;       // 0..15 : pixel group
    const int tng = tid & 15;       // 0..15 : co group
    const int m_base = blockIdx.x * 128;

    // A-load roles: thread handles pixels p0,p1 and ci-quad q0
    const int p0 = tid >> 2;
    const int q0 = tid & 3;
    const int p1 = p0 + 64;
    const int m0 = m_base + p0;
    const int n0 = m0 >> 10, h0 = (m0 >> 5) & 31, w0 = m0 & 31;
    const int m1 = m_base + p1;
    const int n1 = m1 >> 10, h1 = (m1 >> 5) & 31, w1p = m1 & 31;

    // B-load roles
    const int kb = tid >> 5;   // 0..7
    const int cb = tid & 31;   // co quad

    float acc[8][8];
    #pragma unroll
    for (int i=0;i<8;i++)
        #pragma unroll
        for (int j=0;j<8;j++) acc[i][j]=0.f;

    for (int tap=0; tap<9; ++tap){
        const int dh = tap/3 - 1, dw = tap%3 - 1;
        const int hs0=h0+dh, ws0=w0+dw;
        const int hs1=h1+dh, ws1=w1p+dw;
        const bool v0 = ((unsigned)hs0<32u)&&((unsigned)ws0<32u);
        const bool v1 = ((unsigned)hs1<32u)&&((unsigned)ws1<32u);
        const float* src0 = X + ((((n0*32+hs0)*32+ws0)<<7) + (q0<<2));
        const float* src1 = X + ((((n1*32+hs1)*32+ws1)<<7) + (q0<<2));
        const float* wsrc = Wt + (tap*129)*128;

        for (int kc=0; kc<8; ++kc){
            __syncthreads();
            float4 a0 = make_float4(0.f,0.f,0.f,0.f);
            float4 a1 = make_float4(0.f,0.f,0.f,0.f);
            if (v0) a0 = *(const float4*)(src0 + kc*16);
            if (v1) a1 = *(const float4*)(src1 + kc*16);
            const int cb4 = q0*4;
            As[cb4+0][p0]=a0.x; As[cb4+1][p0]=a0.y; As[cb4+2][p0]=a0.z; As[cb4+3][p0]=a0.w;
            As[cb4+0][p1]=a1.x; As[cb4+1][p1]=a1.y; As[cb4+2][p1]=a1.z; As[cb4+3][p1]=a1.w;
            float4 b0 = *(const float4*)(wsrc + (kc*16+kb)*128 + cb*4);
            float4 b1 = *(const float4*)(wsrc + (kc*16+kb+8)*128 + cb*4);
            *(float4*)&Bs[kb][cb*4]   = b0;
            *(float4*)&Bs[kb+8][cb*4] = b1;
            __syncthreads();
            #pragma unroll
            for (int k=0;k<16;++k){
                float4 ta = *(const float4*)&As[k][tmg*8];
                float4 tb = *(const float4*)&As[k][tmg*8+4];
                float4 ua = *(const float4*)&Bs[k][tng*8];
                float4 ub = *(const float4*)&Bs[k][tng*8+4];
                float av[8] = {ta.x,ta.y,ta.z,ta.w,tb.x,tb.y,tb.z,tb.w};
                float bv[8] = {ua.x,ua.y,ua.z,ua.w,ub.x,ub.y,ub.z,ub.w};
                #pragma unroll
                for (int i=0;i<8;i++)
                    #pragma unroll
                    for (int j=0;j<8;j++)
                        acc[i][j] = fmaf(av[i], bv[j], acc[i][j]);
            }
        }
    }

    // epilogue: t-channel (ci==128) contribution with border masks
    int hh[8], wp[8];
    #pragma unroll
    for (int i=0;i<8;i++){
        int m = m_base + tmg*8 + i;
        hh[i] = (m>>5)&31; wp[i] = m&31;
    }
    #pragma unroll
    for (int tap=0;tap<9;++tap){
        int dh=tap/3-1, dw=tap%3-1;
        const float* wtp = Wt + (tap*129+128)*128 + tng*8;
        float4 wa = *(const float4*)(wtp);
        float4 wb = *(const float4*)(wtp+4);
        float wv[8]={wa.x,wa.y,wa.z,wa.w,wb.x,wb.y,wb.z,wb.w};
        #pragma unroll
        for (int i=0;i<8;i++){
            if (((unsigned)(hh[i]+dh)<32u)&&((unsigned)(wp[i]+dw)<32u)){
                #pragma unroll
                for (int j=0;j<8;j++)
                    acc[i][j] = fmaf(tval, wv[j], acc[i][j]);
            }
        }
    }
    float4 ba = *(const float4*)(Bias + tng*8);
    float4 bb = *(const float4*)(Bias + tng*8 + 4);
    float bsv[8]={ba.x,ba.y,ba.z,ba.w,bb.x,bb.y,bb.z,bb.w};
    #pragma unroll
    for (int i=0;i<8;i++){
        int m = m_base + tmg*8 + i;
        float4 o0, o1;
        o0.x = fmaxf(acc[i][0]+bsv[0],0.f);
        o0.y = fmaxf(acc[i][1]+bsv[1],0.f);
        o0.z = fmaxf(acc[i][2]+bsv[2],0.f);
        o0.w = fmaxf(acc[i][3]+bsv[3],0.f);
        o1.x = fmaxf(acc[i][4]+bsv[4],0.f);
        o1.y = fmaxf(acc[i][5]+bsv[5],0.f);
        o1.z = fmaxf(acc[i][6]+bsv[6],0.f);
        o1.w = fmaxf(acc[i][7]+bsv[7],0.f);
        *(float4*)(Out + m*128 + tng*8)   = o0;
        *(float4*)(Out + m*128 + tng*8+4) = o1;
    }
}

// ---- error estimate + deterministic partial reduction ----
__global__ void k_err(){
    if (g_done) return;
    const float dtc = g_dtc;
    double local = 0.0;
    int i0 = blockIdx.x*blockDim.x + threadIdx.x;
    int stride = gridDim.x*blockDim.x;
    for (int i=i0;i<NTOT;i+=stride){
        float e = dtc*(E0c*g_k[0][i] + E2c*g_k[2][i] + E3c*g_k[3][i]
                     + E4c*g_k[4][i] + E5c*g_k[5][i] + E6c*g_k[6][i]);
        float yv = g_y[i], y5v = g_y5[i];
        float sc = 1e-3f + 1e-3f*fmaxf(fabsf(yv), fabsf(y5v));
        float r = e/sc;
        local += (double)r*(double)r;
    }
    __shared__ double sd[256];
    sd[threadIdx.x]=local;
    __syncthreads();
    for (int o=128;o>0;o>>=1){
        if (threadIdx.x<o) sd[threadIdx.x]+=sd[threadIdx.x+o];
        __syncthreads();
    }
    if (threadIdx.x==0) g_part[blockIdx.x]=sd[0];
}

// ---- final reduce + step controller ----
__global__ void k_reduce_ctl(){
    __shared__ double sd[256];
    int tid = threadIdx.x;
    if (g_done){ if (tid==0) g_adv=0; return; }
    double v=0.0;
    for (int i=tid;i<ERR_BLOCKS;i+=256) v += g_part[i];
    sd[tid]=v; __syncthreads();
    for (int o=128;o>0;o>>=1){ if (tid<o) sd[tid]+=sd[tid+o]; __syncthreads(); }
    if (tid==0){
        float err_norm = sqrtf((float)(sd[0] / (double)NTOT));
        err_norm = fmaxf(err_norm, 1e-10f);
        int accept = (err_norm <= 1.0f) ? 1 : 0;
        float factor = 0.9f * powf(err_norm, -0.2f);
        factor = fminf(fmaxf(factor, 0.2f), 10.0f);
        float t = g_t, dtc = g_dtc;
        if (accept) t += dtc;
        g_t = t;
        g_dt = dtc * factor;   // done was false here (matches reference order)
        g_adv = accept;
        if (t >= 1.0f - 1e-6f) g_done = 1;
    }
}

// ---- commit accepted step: y = y5 ----
__global__ void k_commit(){
    if (!g_adv) return;
    const float4* s=(const float4*)g_y5; float4* d=(float4*)g_y;
    int i0=blockIdx.x*blockDim.x+threadIdx.x, st=gridDim.x*blockDim.x;
    for (int q=i0;q<NQ;q+=st) d[q]=s[q];
}

// ---- final output copy ----
__global__ void k_final(float* __restrict__ out){
    const float4* s=(const float4*)g_y; float4* d=(float4*)out;
    int i0=blockIdx.x*blockDim.x+threadIdx.x, st=gridDim.x*blockDim.x;
    for (int q=i0;q<NQ;q+=st) d[q]=s[q];
}

extern "C" void kernel_launch(void* const* d_in, const int* in_sizes, int n_in,
                              void* d_out, int out_size){
    // Robustly map inputs by size: x (NTOT), w1/w2 (WSIZE, in order), b1/b2 (128, in order)
    const float* x = 0; const float* w[2] = {0,0}; const float* b[2] = {0,0};
    int nw=0, nb=0;
    for (int i=0;i<n_in;i++){
        if (in_sizes[i] == NTOT) x = (const float*)d_in[i];
        else if (in_sizes[i] == WSIZE){ if (nw<2) w[nw++] = (const float*)d_in[i]; }
        else if (in_sizes[i] == CH){ if (nb<2) b[nb++] = (const float*)d_in[i]; }
    }
    const float* w1 = w[0]; const float* b1 = b[0];
    const float* w2 = w[1]; const float* b2 = b[1];
    float* out = (float*)d_out;

    k_init<<<EW_BLOCKS,256>>>(x);
    for (int it=0; it<MAX_STEPS; ++it){
        k_ctl_begin<<<1,1>>>();
        for (int s=0;s<7;++s){
            if (s>0) k_combine<<<EW_BLOCKS,256>>>(s);
            int in1 = (s==0)?0 : ((s==6)?2 : 1);
            k_conv<<<NPIX/128,256>>>(w1,b1,s,in1,-1);  // h = relu(conv1(cat(y_s,t))+b1)
            k_conv<<<NPIX/128,256>>>(w2,b2,s,3,s);     // k_s = relu(conv2(cat(h,t))+b2)
        }
        k_err<<<ERR_BLOCKS,256>>>();
        k_reduce_ctl<<<1,256>>>();
        k_commit<<<EW_BLOCKS,256>>>();
    }
    k_final<<<EW_BLOCKS,256>>>(out);
}

// round 3
// speedup vs baseline: 2.0763x; 2.0763x over previous
#include <cuda_runtime.h>
#include <cuda_bf16.h>
#include <stdint.h>
#include <math.h>

#define CH 128
#define NPIX 32768              // 32*32*32
#define NTOT (NPIX*CH)          // 4194304
#define NQ (NTOT/4)
#define WSIZE (3*3*129*128)
#define NWB (9*128*128)         // 147456
#define MAX_STEPS 32
#define EW_BLOCKS 512
#define ERR_BLOCKS 1024

// ---- Dormand-Prince coefficients ----
#define C10 0.2f
#define C20 ((float)(3.0/40.0))
#define C21 ((float)(9.0/40.0))
#define C30 ((float)(44.0/45.0))
#define C31 ((float)(-56.0/15.0))
#define C32 ((float)(32.0/9.0))
#define C40 ((float)(19372.0/6561.0))
#define C41 ((float)(-25360.0/2187.0))
#define C42 ((float)(64448.0/6561.0))
#define C43 ((float)(-212.0/729.0))
#define C50 ((float)(9017.0/3168.0))
#define C51 ((float)(-355.0/33.0))
#define C52 ((float)(46732.0/5247.0))
#define C53 ((float)(49.0/176.0))
#define C54 ((float)(-5103.0/18656.0))
#define B0c ((float)(35.0/384.0))
#define B2c ((float)(500.0/1113.0))
#define B3c ((float)(125.0/192.0))
#define B4c ((float)(-2187.0/6784.0))
#define B5c ((float)(11.0/84.0))
#define E0c ((float)(35.0/384.0 - 5179.0/57600.0))
#define E2c ((float)(500.0/1113.0 - 7571.0/16695.0))
#define E3c ((float)(125.0/192.0 - 393.0/640.0))
#define E4c ((float)(-2187.0/6784.0 + 92097.0/339200.0))
#define E5c ((float)(11.0/84.0 - 187.0/2100.0))
#define E6c ((float)(-1.0/40.0))

// ---- Persistent state ----
__device__ __align__(16) float g_yf[2][NTOT];        // ping-pong fp32 y
__device__ __align__(16) float g_k[7][NTOT];
__device__ __align__(16) __nv_bfloat16 g_yh[2][NTOT], g_yl[2][NTOT];
__device__ __align__(16) __nv_bfloat16 g_tmph[NTOT],  g_tmpl[NTOT];
__device__ __align__(16) __nv_bfloat16 g_hh[NTOT],    g_hl[NTOT];
__device__ __align__(16) __nv_bfloat16 g_wbh[2][NWB], g_wbl[2][NWB]; // [conv][tap*16384+co*128+ci]
__device__ float g_tw[2][9][128];
__device__ double g_part[ERR_BLOCKS];
__device__ float g_t, g_dt, g_dtc, g_ts7[7];
__device__ int g_done, g_cur;

// ---- smem layout for conv: 2 stages of {Ah, Al, Wh, Wl}, each 128 rows x 80B ----
#define TILE_B 10240
#define AH_OFF 0
#define AL_OFF 10240
#define WH_OFF 20480
#define WL_OFF 30720
#define STG    40960
#define CONV_SMEM (2*STG)

// ============ PTX wrappers (all base-ISA, valid for compute_103) ============
__device__ __forceinline__ uint32_t smem_u32(const void* p){
    uint32_t a;
    asm("{ .reg .u64 t; cvta.to.shared.u64 t, %1; cvt.u32.u64 %0, t; }" : "=r"(a) : "l"(p));
    return a;
}
__device__ __forceinline__ void cpa16(uint32_t dst, const void* src, uint32_t sz){
    asm volatile("cp.async.cg.shared.global [%0], [%1], 16, %2;" :: "r"(dst), "l"(src), "r"(sz));
}
#define CP_COMMIT() asm volatile("cp.async.commit_group;" ::: "memory")
#define CP_WAIT1()  asm volatile("cp.async.wait_group 1;" ::: "memory")
#define CP_WAIT0()  asm volatile("cp.async.wait_group 0;" ::: "memory")

__device__ __forceinline__ void ldm4(uint32_t* r, uint32_t addr){
    asm volatile("ldmatrix.sync.aligned.m8n8.x4.shared.b16 {%0,%1,%2,%3}, [%4];"
        : "=r"(r[0]), "=r"(r[1]), "=r"(r[2]), "=r"(r[3]) : "r"(addr));
}
__device__ __forceinline__ void mma16816(float* c, const uint32_t* a, uint32_t b0, uint32_t b1){
    asm volatile("mma.sync.aligned.m16n8k16.row.col.f32.bf16.bf16.f32 "
        "{%0,%1,%2,%3}, {%4,%5,%6,%7}, {%8,%9}, {%0,%1,%2,%3};"
        : "+f"(c[0]), "+f"(c[1]), "+f"(c[2]), "+f"(c[3])
        : "r"(a[0]), "r"(a[1]), "r"(a[2]), "r"(a[3]), "r"(b0), "r"(b1));
}

// ---- bf16 split helpers ----
__device__ __forceinline__ uint32_t pk2(__nv_bfloat16 a, __nv_bfloat16 b){
    return (uint32_t)__bfloat16_as_ushort(a) | ((uint32_t)__bfloat16_as_ushort(b) << 16);
}
__device__ __forceinline__ void split_store4(__nv_bfloat16* Hp, __nv_bfloat16* Lp, int e, float4 v){
    __nv_bfloat16 h0=__float2bfloat16(v.x), h1=__float2bfloat16(v.y),
                  h2=__float2bfloat16(v.z), h3=__float2bfloat16(v.w);
    float l0=v.x-__bfloat162float(h0), l1=v.y-__bfloat162float(h1),
          l2=v.z-__bfloat162float(h2), l3=v.w-__bfloat162float(h3);
    uint2 H = make_uint2(pk2(h0,h1), pk2(h2,h3));
    uint2 L = make_uint2(pk2(__float2bfloat16(l0),__float2bfloat16(l1)),
                         pk2(__float2bfloat16(l2),__float2bfloat16(l3)));
    *(uint2*)(Hp + e) = H;
    *(uint2*)(Lp + e) = L;
}

// ============ weight prep ============
__global__ void k_prep_w(const float* __restrict__ w1, const float* __restrict__ w2){
    int i = blockIdx.x*blockDim.x + threadIdx.x;
    if (i >= 2*NWB) return;
    int conv = i / NWB, r = i % NWB;
    int tap = r >> 14, co = (r >> 7) & 127, ci = r & 127;
    float v = (conv ? w2 : w1)[(tap*129 + ci)*128 + co];
    __nv_bfloat16 hb = __float2bfloat16(v);
    g_wbh[conv][r] = hb;
    g_wbl[conv][r] = __float2bfloat16(v - __bfloat162float(hb));
}
__global__ void k_prep_tw(const float* __restrict__ w1, const float* __restrict__ w2){
    int tid = threadIdx.x;
    int conv = tid >> 7, co = tid & 127;
    const float* w = conv ? w2 : w1;
    for (int cat=0; cat<9; cat++){
        int hc = cat/3, wc = cat%3;
        float s = 0.f;
        for (int tap=0; tap<9; tap++){
            int dh = tap/3 - 1, dw = tap%3 - 1;
            bool okh = !((hc==0 && dh<0) || (hc==2 && dh>0));
            bool okw = !((wc==0 && dw<0) || (wc==2 && dw>0));
            if (okh && okw) s += w[(tap*129 + 128)*128 + co];
        }
        g_tw[conv][cat][co] = s;
    }
}

// ============ init / elementwise / control ============
__global__ void k_init(const float* __restrict__ x){
    int i = blockIdx.x*blockDim.x + threadIdx.x;
    if (i == 0){
        g_t=0.f; g_dt=0.05f; g_done=0; g_cur=0;
        float dtc = fminf(0.05f, 1.0f);
        g_dtc = dtc;
        g_ts7[0]=0.f;        g_ts7[1]=0.2f*dtc;  g_ts7[2]=0.3f*dtc;
        g_ts7[3]=0.8f*dtc;   g_ts7[4]=((float)(8.0/9.0))*dtc;
        g_ts7[5]=dtc;        g_ts7[6]=dtc;
    }
    const float4* xs=(const float4*)x; float4* ys=(float4*)g_yf[0];
    int st = gridDim.x*blockDim.x;
    for (int q=i; q<NQ; q+=st){
        float4 v = xs[q];
        ys[q] = v;
        split_store4(g_yh[0], g_yl[0], q*4, v);
    }
}

__global__ void k_combine(int s){
    if (g_done) return;
    const float dtc = g_dtc;
    const int cur = g_cur, nx = cur^1;
    int i0 = blockIdx.x*blockDim.x + threadIdx.x;
    int stride = gridDim.x*blockDim.x;
    const float4 *Y=(const float4*)g_yf[cur];
    const float4 *K0=(const float4*)g_k[0], *K1=(const float4*)g_k[1],
                 *K2=(const float4*)g_k[2], *K3=(const float4*)g_k[3],
                 *K4=(const float4*)g_k[4], *K5=(const float4*)g_k[5];
    for (int q=i0; q<NQ; q+=stride){
        float4 y = Y[q], v;
        if (s==1){
            float4 a=K0[q];
            v = make_float4(y.x+dtc*(C10*a.x), y.y+dtc*(C10*a.y), y.z+dtc*(C10*a.z), y.w+dtc*(C10*a.w));
        } else if (s==2){
            float4 a=K0[q], b=K1[q];
            v = make_float4(y.x+dtc*(C20*a.x+C21*b.x), y.y+dtc*(C20*a.y+C21*b.y),
                            y.z+dtc*(C20*a.z+C21*b.z), y.w+dtc*(C20*a.w+C21*b.w));
        } else if (s==3){
            float4 a=K0[q], b=K1[q], c=K2[q];
            v = make_float4(y.x+dtc*(C30*a.x+C31*b.x+C32*c.x), y.y+dtc*(C30*a.y+C31*b.y+C32*c.y),
                            y.z+dtc*(C30*a.z+C31*b.z+C32*c.z), y.w+dtc*(C30*a.w+C31*b.w+C32*c.w));
        } else if (s==4){
            float4 a=K0[q], b=K1[q], c=K2[q], d=K3[q];
            v = make_float4(y.x+dtc*(C40*a.x+C41*b.x+C42*c.x+C43*d.x),
                            y.y+dtc*(C40*a.y+C41*b.y+C42*c.y+C43*d.y),
                            y.z+dtc*(C40*a.z+C41*b.z+C42*c.z+C43*d.z),
                            y.w+dtc*(C40*a.w+C41*b.w+C42*c.w+C43*d.w));
        } else if (s==5){
            float4 a=K0[q], b=K1[q], c=K2[q], d=K3[q], e=K4[q];
            v = make_float4(y.x+dtc*(C50*a.x+C51*b.x+C52*c.x+C53*d.x+C54*e.x),
                            y.y+dtc*(C50*a.y+C51*b.y+C52*c.y+C53*d.y+C54*e.y),
                            y.z+dtc*(C50*a.z+C51*b.z+C52*c.z+C53*d.z+C54*e.z),
                            y.w+dtc*(C50*a.w+C51*b.w+C52*c.w+C53*d.w+C54*e.w));
        } else {
            float4 a=K0[q], c=K2[q], d=K3[q], e=K4[q], f=K5[q];
            v = make_float4(y.x+dtc*(B0c*a.x+B2c*c.x+B3c*d.x+B4c*e.x+B5c*f.x),
                            y.y+dtc*(B0c*a.y+B2c*c.y+B3c*d.y+B4c*e.y+B5c*f.y),
                            y.z+dtc*(B0c*a.z+B2c*c.z+B3c*d.z+B4c*e.z+B5c*f.z),
                            y.w+dtc*(B0c*a.w+B2c*c.w+B3c*d.w+B4c*e.w+B5c*f.w));
        }
        if (s==6){
            ((float4*)g_yf[nx])[q] = v;
            split_store4(g_yh[nx], g_yl[nx], q*4, v);
        } else {
            split_store4(g_tmph, g_tmpl, q*4, v);
        }
    }
}

__global__ void k_err(){
    if (g_done) return;
    const float dtc = g_dtc;
    const int cur = g_cur, nx = cur^1;
    double local = 0.0;
    int i0 = blockIdx.x*blockDim.x + threadIdx.x;
    int stride = gridDim.x*blockDim.x;
    for (int i=i0; i<NTOT; i+=stride){
        float e = dtc*(E0c*g_k[0][i] + E2c*g_k[2][i] + E3c*g_k[3][i]
                     + E4c*g_k[4][i] + E5c*g_k[5][i] + E6c*g_k[6][i]);
        float yv = g_yf[cur][i], y5v = g_yf[nx][i];
        float sc = 1e-3f + 1e-3f*fmaxf(fabsf(yv), fabsf(y5v));
        float r = e/sc;
        local += (double)r*(double)r;
    }
    __shared__ double sd[256];
    sd[threadIdx.x] = local;
    __syncthreads();
    for (int o=128; o>0; o>>=1){
        if (threadIdx.x < o) sd[threadIdx.x] += sd[threadIdx.x+o];
        __syncthreads();
    }
    if (threadIdx.x==0) g_part[blockIdx.x] = sd[0];
}

__global__ void k_reduce_ctl(){
    __shared__ double sd[256];
    int tid = threadIdx.x;
    if (g_done) return;
    double v=0.0;
    for (int i=tid; i<ERR_BLOCKS; i+=256) v += g_part[i];
    sd[tid]=v; __syncthreads();
    for (int o=128; o>0; o>>=1){ if (tid<o) sd[tid]+=sd[tid+o]; __syncthreads(); }
    if (tid==0){
        float err_norm = sqrtf((float)(sd[0] / (double)NTOT));
        err_norm = fmaxf(err_norm, 1e-10f);
        int accept = (err_norm <= 1.0f) ? 1 : 0;
        float factor = 0.9f * powf(err_norm, -0.2f);
        factor = fminf(fmaxf(factor, 0.2f), 10.0f);
        float t = g_t, dtc = g_dtc;
        if (accept){ t += dtc; g_cur ^= 1; }
        float dt = dtc * factor;
        g_t = t; g_dt = dt;
        if (t >= 1.0f - 1e-6f){ g_done = 1; return; }
        float dtc2 = fminf(dt, 1.0f - t);
        g_dtc = dtc2;
        g_ts7[0]=t;           g_ts7[1]=t+0.2f*dtc2;  g_ts7[2]=t+0.3f*dtc2;
        g_ts7[3]=t+0.8f*dtc2; g_ts7[4]=t+((float)(8.0/9.0))*dtc2;
        g_ts7[5]=t+dtc2;      g_ts7[6]=t+dtc2;
    }
}

__global__ void k_final(float* __restrict__ out){
    const float4* s=(const float4*)g_yf[g_cur]; float4* d=(float4*)out;
    int i0=blockIdx.x*blockDim.x+threadIdx.x, st=gridDim.x*blockDim.x;
    for (int q=i0; q<NQ; q+=st) d[q]=s[q];
}

// ============ HMMA conv: 128 pix x 128 co per CTA, K = 9 taps x 128 ci, hi/lo 3-pass ============
__global__ __launch_bounds__(256,2)
void k_conv(const float* __restrict__ Bias, int wsel, int s, int in_sel, int out_sel)
{
    if (g_done) return;
    extern __shared__ __align__(16) char dsm[];
    const uint32_t sb = smem_u32(dsm);

    const int tid  = threadIdx.x;
    const int wid  = tid >> 5;
    const int lane = tid & 31;

    const int cur = g_cur;
    const __nv_bfloat16 *Xh, *Xl;
    if      (in_sel==0){ Xh=g_yh[cur];   Xl=g_yl[cur];   }
    else if (in_sel==1){ Xh=g_tmph;      Xl=g_tmpl;      }
    else if (in_sel==2){ Xh=g_yh[cur^1]; Xl=g_yl[cur^1]; }
    else               { Xh=g_hh;        Xl=g_hl;        }
    const __nv_bfloat16* __restrict__ WHg = g_wbh[wsel];
    const __nv_bfloat16* __restrict__ WLg = g_wbl[wsel];
    const float tval = g_ts7[s];

    // ---- loader geometry: 2 slots per thread, slot -> (row 0..127, seg 0..3) ----
    int rowA[2], segA[2], pxn[2], pxh[2], pxw[2];
    #pragma unroll
    for (int j=0;j<2;j++){
        int sl = tid + j*256;
        rowA[j] = sl >> 2; segA[j] = sl & 3;
        int m = blockIdx.x*128 + rowA[j];
        pxn[j] = (m >> 10) << 10;
        pxh[j] = (m >> 5) & 31;
        pxw[j] = m & 31;
    }

    // ---- compute geometry ----
    const int m0 = (wid & 3) * 32;
    const int n0 = (wid >> 2) * 64;
    const uint32_t aoffbase = (uint32_t)((m0 + (lane & 15))*80 + ((lane >> 4)*8)*2);
    const uint32_t boffbase = (uint32_t)((n0 + (lane & 7) + ((lane >> 4) << 3))*80 + (((lane >> 3) & 1)*8)*2);

    float acc[2][8][4];
    #pragma unroll
    for (int i=0;i<2;i++)
        #pragma unroll
        for (int j=0;j<8;j++)
            #pragma unroll
            for (int q=0;q<4;q++) acc[i][j][q]=0.f;

    // ---- chunk loader (cp.async) ----
    auto load_chunk = [&](int c, int st){
        int tap = c >> 2, q = c & 3, ci0 = q << 5;
        int dh = tap/3 - 1, dw = tap - (tap/3)*3 - 1;
        uint32_t base = sb + st*STG;
        int wbase = tap*16384 + ci0;
        #pragma unroll
        for (int j=0;j<2;j++){
            int row = rowA[j], seg = segA[j];
            uint32_t dA = base + (uint32_t)(row*80 + seg*16);
            int hs = pxh[j] + dh, ws = pxw[j] + dw;
            bool v = ((unsigned)hs < 32u) && ((unsigned)ws < 32u);
            long off = v ? ((long)((pxn[j] + hs*32 + ws)) << 7) + ci0 + seg*8 : 0;
            uint32_t sz = v ? 16u : 0u;
            cpa16(dA + AH_OFF, Xh + off, sz);
            cpa16(dA + AL_OFF, Xl + off, sz);
            int woff = wbase + row*128 + seg*8;
            cpa16(dA + WH_OFF, WHg + woff, 16u);
            cpa16(dA + WL_OFF, WLg + woff, 16u);
        }
    };

    load_chunk(0, 0);
    CP_COMMIT();

    #pragma unroll 1
    for (int c=0; c<36; ++c){
        const int st = c & 1;
        if (c < 35){
            load_chunk(c+1, st^1);
            CP_COMMIT();
            CP_WAIT1();
        } else {
            CP_WAIT0();
        }
        __syncthreads();

        const uint32_t cb = sb + st*STG;
        #pragma unroll
        for (int pass=0; pass<3; ++pass){
            const uint32_t aoff = cb + ((pass==1)?AL_OFF:AH_OFF) + aoffbase;
            const uint32_t boff = cb + ((pass==2)?WL_OFF:WH_OFF) + boffbase;
            #pragma unroll
            for (int k16=0; k16<2; ++k16){
                const uint32_t kbyte = (uint32_t)(k16*32);
                uint32_t a0[4], a1[4];
                ldm4(a0, aoff + kbyte);
                ldm4(a1, aoff + 16*80 + kbyte);
                #pragma unroll
                for (int j=0;j<4;j++){
                    uint32_t b[4];
                    ldm4(b, boff + (uint32_t)(j*16*80) + kbyte);
                    mma16816(acc[0][2*j],   a0, b[0], b[1]);
                    mma16816(acc[0][2*j+1], a0, b[2], b[3]);
                    mma16816(acc[1][2*j],   a1, b[0], b[1]);
                    mma16816(acc[1][2*j+1], a1, b[2], b[3]);
                }
            }
        }
        __syncthreads();
    }

    // ---- epilogue: + t-channel + bias, relu, store ----
    const int gID = lane >> 2, tq = lane & 3;
    #pragma unroll
    for (int mf=0; mf<2; ++mf){
        #pragma unroll
        for (int rr=0; rr<2; ++rr){
            int r = m0 + mf*16 + rr*8 + gID;
            int m = blockIdx.x*128 + r;
            int hp = (m >> 5) & 31, wp = m & 31;
            int cat = ((hp==0)?0:(hp==31)?6:3) + ((wp==0)?0:(wp==31)?2:1);
            const float* tw = g_tw[wsel][cat];
            #pragma unroll
            for (int nf=0; nf<8; ++nf){
                int col = n0 + nf*8 + tq*2;
                float v0 = fmaxf(acc[mf][nf][rr*2+0] + tval*tw[col]   + Bias[col],   0.f);
                float v1 = fmaxf(acc[mf][nf][rr*2+1] + tval*tw[col+1] + Bias[col+1], 0.f);
                if (out_sel >= 0){
                    *(float2*)(g_k[out_sel] + m*128 + col) = make_float2(v0, v1);
                } else {
                    __nv_bfloat16 h0=__float2bfloat16(v0), h1=__float2bfloat16(v1);
                    float l0=v0-__bfloat162float(h0), l1=v1-__bfloat162float(h1);
                    *(uint32_t*)(g_hh + m*128 + col) = pk2(h0, h1);
                    *(uint32_t*)(g_hl + m*128 + col) = pk2(__float2bfloat16(l0), __float2bfloat16(l1));
                }
            }
        }
    }
}

// ============ launch ============
extern "C" void kernel_launch(void* const* d_in, const int* in_sizes, int n_in,
                              void* d_out, int out_size){
    const float* x = 0; const float* w[2] = {0,0}; const float* b[2] = {0,0};
    int nw=0, nb_=0;
    for (int i=0;i<n_in;i++){
        if (in_sizes[i] == NTOT) x = (const float*)d_in[i];
        else if (in_sizes[i] == WSIZE){ if (nw<2) w[nw++] = (const float*)d_in[i]; }
        else if (in_sizes[i] == CH){ if (nb_<2) b[nb_++] = (const float*)d_in[i]; }
    }
    const float* w1=w[0]; const float* b1=b[0];
    const float* w2=w[1]; const float* b2=b[1];
    float* out = (float*)d_out;

    cudaFuncSetAttribute(k_conv, cudaFuncAttributeMaxDynamicSharedMemorySize, CONV_SMEM);

    k_prep_w<<<(2*NWB + 255)/256, 256>>>(w1, w2);
    k_prep_tw<<<1, 256>>>(w1, w2);
    k_init<<<EW_BLOCKS, 256>>>(x);

    for (int it=0; it<MAX_STEPS; ++it){
        for (int s=0;s<7;++s){
            if (s > 0) k_combine<<<EW_BLOCKS,256>>>(s);
            int in1 = (s==0) ? 0 : ((s==6) ? 2 : 1);
            k_conv<<<256,256,CONV_SMEM>>>(b1, 0, s, in1, -1);  // h = relu(conv1(cat(y_s,t))+b1)
            k_conv<<<256,256,CONV_SMEM>>>(b2, 1, s, 3, s);     // k_s = relu(conv2(cat(h,t))+b2)
        }
        k_err<<<ERR_BLOCKS,256>>>();
        k_reduce_ctl<<<1,256>>>();
    }
    k_final<<<EW_BLOCKS,256>>>(out);
}

// round 4
// speedup vs baseline: 3.3476x; 1.6123x over previous
#include <cuda_runtime.h>
#include <cuda_fp16.h>
#include <stdint.h>
#include <math.h>

#define CH 128
#define NPIX 32768              // 32*32*32
#define NTOT (NPIX*CH)          // 4194304
#define NQ (NTOT/4)
#define WSIZE (3*3*129*128)
#define NWB (9*128*128)         // 147456
#define MAX_STEPS 32
#define EW_BLOCKS 512
#define ERR_BLOCKS 1024

// ---- Dormand-Prince coefficients ----
#define C10 0.2f
#define C20 ((float)(3.0/40.0))
#define C21 ((float)(9.0/40.0))
#define C30 ((float)(44.0/45.0))
#define C31 ((float)(-56.0/15.0))
#define C32 ((float)(32.0/9.0))
#define C40 ((float)(19372.0/6561.0))
#define C41 ((float)(-25360.0/2187.0))
#define C42 ((float)(64448.0/6561.0))
#define C43 ((float)(-212.0/729.0))
#define C50 ((float)(9017.0/3168.0))
#define C51 ((float)(-355.0/33.0))
#define C52 ((float)(46732.0/5247.0))
#define C53 ((float)(49.0/176.0))
#define C54 ((float)(-5103.0/18656.0))
#define B0c ((float)(35.0/384.0))
#define B2c ((float)(500.0/1113.0))
#define B3c ((float)(125.0/192.0))
#define B4c ((float)(-2187.0/6784.0))
#define B5c ((float)(11.0/84.0))
#define E0c ((float)(35.0/384.0 - 5179.0/57600.0))
#define E2c ((float)(500.0/1113.0 - 7571.0/16695.0))
#define E3c ((float)(125.0/192.0 - 393.0/640.0))
#define E4c ((float)(-2187.0/6784.0 + 92097.0/339200.0))
#define E5c ((float)(11.0/84.0 - 187.0/2100.0))
#define E6c ((float)(-1.0/40.0))

// ---- Persistent state ----
__device__ __align__(16) float g_yf[2][NTOT];        // ping-pong fp32 y (cur, and y5 in cur^1)
__device__ __align__(16) float g_k[7][NTOT];
__device__ __align__(16) __half g_yh[2][NTOT];       // fp16 mirrors of g_yf
__device__ __align__(16) __half g_tmph[NTOT];
__device__ __align__(16) __half g_hh[NTOT];
__device__ __align__(16) __half g_wh[2][NWB];        // [conv][tap*16384 + co*128 + ci]
__device__ float g_tw[2][9][128];
__device__ double g_part[ERR_BLOCKS];
__device__ float g_t, g_dt, g_dtc, g_ts7[7];
__device__ int g_done, g_cur;

// ---- conv smem: 2 stages of {A, W}; rows 128 x (64 fp16 = 128B + 16B pad = 144B) ----
#define ROWB 144
#define TILE_B (128*ROWB)        // 18432
#define A_OFF 0
#define W_OFF TILE_B
#define STG   (2*TILE_B)         // 36864
#define CONV_SMEM (2*STG)        // 73728

// ============ PTX wrappers (base ISA, valid for compute_103) ============
__device__ __forceinline__ uint32_t smem_u32(const void* p){
    uint32_t a;
    asm("{ .reg .u64 t; cvta.to.shared.u64 t, %1; cvt.u32.u64 %0, t; }" : "=r"(a) : "l"(p));
    return a;
}
__device__ __forceinline__ void cpa16(uint32_t dst, const void* src, uint32_t sz){
    asm volatile("cp.async.cg.shared.global [%0], [%1], 16, %2;" :: "r"(dst), "l"(src), "r"(sz));
}
#define CP_COMMIT() asm volatile("cp.async.commit_group;" ::: "memory")
#define CP_WAIT1()  asm volatile("cp.async.wait_group 1;" ::: "memory")
#define CP_WAIT0()  asm volatile("cp.async.wait_group 0;" ::: "memory")

__device__ __forceinline__ void ldm4(uint32_t* r, uint32_t addr){
    asm volatile("ldmatrix.sync.aligned.m8n8.x4.shared.b16 {%0,%1,%2,%3}, [%4];"
        : "=r"(r[0]), "=r"(r[1]), "=r"(r[2]), "=r"(r[3]) : "r"(addr));
}
__device__ __forceinline__ void mma16816(float* c, const uint32_t* a, uint32_t b0, uint32_t b1){
    asm volatile("mma.sync.aligned.m16n8k16.row.col.f32.f16.f16.f32 "
        "{%0,%1,%2,%3}, {%4,%5,%6,%7}, {%8,%9}, {%0,%1,%2,%3};"
        : "+f"(c[0]), "+f"(c[1]), "+f"(c[2]), "+f"(c[3])
        : "r"(a[0]), "r"(a[1]), "r"(a[2]), "r"(a[3]), "r"(b0), "r"(b1));
}

__device__ __forceinline__ uint32_t pk2h(__half a, __half b){
    return (uint32_t)__half_as_ushort(a) | ((uint32_t)__half_as_ushort(b) << 16);
}
__device__ __forceinline__ void h_store4(__half* Hp, int e, float4 v){
    uint2 H = make_uint2(pk2h(__float2half(v.x), __float2half(v.y)),
                         pk2h(__float2half(v.z), __float2half(v.w)));
    *(uint2*)(Hp + e) = H;
}

// ============ weight prep ============
__global__ void k_prep_w(const float* __restrict__ w1, const float* __restrict__ w2){
    int i = blockIdx.x*blockDim.x + threadIdx.x;
    if (i >= 2*NWB) return;
    int conv = i / NWB, r = i % NWB;
    int tap = r >> 14, co = (r >> 7) & 127, ci = r & 127;
    float v = (conv ? w2 : w1)[(tap*129 + ci)*128 + co];
    g_wh[conv][r] = __float2half(v);
}
__global__ void k_prep_tw(const float* __restrict__ w1, const float* __restrict__ w2){
    int tid = threadIdx.x;
    int conv = tid >> 7, co = tid & 127;
    const float* w = conv ? w2 : w1;
    for (int cat=0; cat<9; cat++){
        int hc = cat/3, wc = cat%3;
        float s = 0.f;
        for (int tap=0; tap<9; tap++){
            int dh = tap/3 - 1, dw = tap%3 - 1;
            bool okh = !((hc==0 && dh<0) || (hc==2 && dh>0));
            bool okw = !((wc==0 && dw<0) || (wc==2 && dw>0));
            if (okh && okw) s += w[(tap*129 + 128)*128 + co];
        }
        g_tw[conv][cat][co] = s;
    }
}

// ============ init / elementwise / control ============
__global__ void k_init(const float* __restrict__ x){
    int i = blockIdx.x*blockDim.x + threadIdx.x;
    if (i == 0){
        g_t=0.f; g_dt=0.05f; g_done=0; g_cur=0;
        float dtc = 0.05f;
        g_dtc = dtc;
        g_ts7[0]=0.f;        g_ts7[1]=0.2f*dtc;  g_ts7[2]=0.3f*dtc;
        g_ts7[3]=0.8f*dtc;   g_ts7[4]=((float)(8.0/9.0))*dtc;
        g_ts7[5]=dtc;        g_ts7[6]=dtc;
    }
    const float4* xs=(const float4*)x; float4* ys=(float4*)g_yf[0];
    int st = gridDim.x*blockDim.x;
    for (int q=i; q<NQ; q+=st){
        float4 v = xs[q];
        ys[q] = v;
        h_store4(g_yh[0], q*4, v);
    }
}

__global__ void k_combine(int s){
    if (g_done) return;
    const float dtc = g_dtc;
    const int cur = g_cur, nx = cur^1;
    int i0 = blockIdx.x*blockDim.x + threadIdx.x;
    int stride = gridDim.x*blockDim.x;
    const float4 *Y=(const float4*)g_yf[cur];
    const float4 *K0=(const float4*)g_k[0], *K1=(const float4*)g_k[1],
                 *K2=(const float4*)g_k[2], *K3=(const float4*)g_k[3],
                 *K4=(const float4*)g_k[4], *K5=(const float4*)g_k[5];
    for (int q=i0; q<NQ; q+=stride){
        float4 y = Y[q], v;
        if (s==1){
            float4 a=K0[q];
            v = make_float4(y.x+dtc*(C10*a.x), y.y+dtc*(C10*a.y), y.z+dtc*(C10*a.z), y.w+dtc*(C10*a.w));
        } else if (s==2){
            float4 a=K0[q], b=K1[q];
            v = make_float4(y.x+dtc*(C20*a.x+C21*b.x), y.y+dtc*(C20*a.y+C21*b.y),
                            y.z+dtc*(C20*a.z+C21*b.z), y.w+dtc*(C20*a.w+C21*b.w));
        } else if (s==3){
            float4 a=K0[q], b=K1[q], c=K2[q];
            v = make_float4(y.x+dtc*(C30*a.x+C31*b.x+C32*c.x), y.y+dtc*(C30*a.y+C31*b.y+C32*c.y),
                            y.z+dtc*(C30*a.z+C31*b.z+C32*c.z), y.w+dtc*(C30*a.w+C31*b.w+C32*c.w));
        } else if (s==4){
            float4 a=K0[q], b=K1[q], c=K2[q], d=K3[q];
            v = make_float4(y.x+dtc*(C40*a.x+C41*b.x+C42*c.x+C43*d.x),
                            y.y+dtc*(C40*a.y+C41*b.y+C42*c.y+C43*d.y),
                            y.z+dtc*(C40*a.z+C41*b.z+C42*c.z+C43*d.z),
                            y.w+dtc*(C40*a.w+C41*b.w+C42*c.w+C43*d.w));
        } else if (s==5){
            float4 a=K0[q], b=K1[q], c=K2[q], d=K3[q], e=K4[q];
            v = make_float4(y.x+dtc*(C50*a.x+C51*b.x+C52*c.x+C53*d.x+C54*e.x),
                            y.y+dtc*(C50*a.y+C51*b.y+C52*c.y+C53*d.y+C54*e.y),
                            y.z+dtc*(C50*a.z+C51*b.z+C52*c.z+C53*d.z+C54*e.z),
                            y.w+dtc*(C50*a.w+C51*b.w+C52*c.w+C53*d.w+C54*e.w));
        } else {
            float4 a=K0[q], c=K2[q], d=K3[q], e=K4[q], f=K5[q];
            v = make_float4(y.x+dtc*(B0c*a.x+B2c*c.x+B3c*d.x+B4c*e.x+B5c*f.x),
                            y.y+dtc*(B0c*a.y+B2c*c.y+B3c*d.y+B4c*e.y+B5c*f.y),
                            y.z+dtc*(B0c*a.z+B2c*c.z+B3c*d.z+B4c*e.z+B5c*f.z),
                            y.w+dtc*(B0c*a.w+B2c*c.w+B3c*d.w+B4c*e.w+B5c*f.w));
        }
        if (s==6){
            ((float4*)g_yf[nx])[q] = v;
            h_store4(g_yh[nx], q*4, v);
        } else {
            h_store4(g_tmph, q*4, v);
        }
    }
}

__global__ void k_err(){
    if (g_done) return;
    const float dtc = g_dtc;
    const int cur = g_cur, nx = cur^1;
    double local = 0.0;
    int i0 = blockIdx.x*blockDim.x + threadIdx.x;
    int stride = gridDim.x*blockDim.x;
    for (int i=i0; i<NTOT; i+=stride){
        float e = dtc*(E0c*g_k[0][i] + E2c*g_k[2][i] + E3c*g_k[3][i]
                     + E4c*g_k[4][i] + E5c*g_k[5][i] + E6c*g_k[6][i]);
        float yv = g_yf[cur][i], y5v = g_yf[nx][i];
        float sc = 1e-3f + 1e-3f*fmaxf(fabsf(yv), fabsf(y5v));
        float r = e/sc;
        local += (double)r*(double)r;
    }
    __shared__ double sd[256];
    sd[threadIdx.x] = local;
    __syncthreads();
    for (int o=128; o>0; o>>=1){
        if (threadIdx.x < o) sd[threadIdx.x] += sd[threadIdx.x+o];
        __syncthreads();
    }
    if (threadIdx.x==0) g_part[blockIdx.x] = sd[0];
}

__global__ void k_reduce_ctl(){
    __shared__ double sd[256];
    int tid = threadIdx.x;
    if (g_done) return;
    double v=0.0;
    for (int i=tid; i<ERR_BLOCKS; i+=256) v += g_part[i];
    sd[tid]=v; __syncthreads();
    for (int o=128; o>0; o>>=1){ if (tid<o) sd[tid]+=sd[tid+o]; __syncthreads(); }
    if (tid==0){
        float err_norm = sqrtf((float)(sd[0] / (double)NTOT));
        err_norm = fmaxf(err_norm, 1e-10f);
        int accept = (err_norm <= 1.0f) ? 1 : 0;
        float factor = 0.9f * powf(err_norm, -0.2f);
        factor = fminf(fmaxf(factor, 0.2f), 10.0f);
        float t = g_t, dtc = g_dtc;
        if (accept){ t += dtc; g_cur ^= 1; }
        float dt = dtc * factor;
        g_t = t; g_dt = dt;
        if (t >= 1.0f - 1e-6f){ g_done = 1; return; }
        float dtc2 = fminf(dt, 1.0f - t);
        g_dtc = dtc2;
        g_ts7[0]=t;           g_ts7[1]=t+0.2f*dtc2;  g_ts7[2]=t+0.3f*dtc2;
        g_ts7[3]=t+0.8f*dtc2; g_ts7[4]=t+((float)(8.0/9.0))*dtc2;
        g_ts7[5]=t+dtc2;      g_ts7[6]=t+dtc2;
    }
}

__global__ void k_final(float* __restrict__ out){
    const float4* s=(const float4*)g_yf[g_cur]; float4* d=(float4*)out;
    int i0=blockIdx.x*blockDim.x+threadIdx.x, st=gridDim.x*blockDim.x;
    for (int q=i0; q<NQ; q+=st) d[q]=s[q];
}

// ============ HMMA conv: 128 pix x 128 co per CTA, K = 9 taps x 128 ci, fp16 single-pass ============
__global__ __launch_bounds__(256,2)
void k_conv(const float* __restrict__ Bias, int wsel, int s, int in_sel, int out_sel)
{
    if (g_done) return;
    extern __shared__ __align__(16) char dsm[];
    const uint32_t sb = smem_u32(dsm);

    const int tid  = threadIdx.x;
    const int wid  = tid >> 5;
    const int lane = tid & 31;

    const int cur = g_cur;
    const __half* __restrict__ X =
        (in_sel==0) ? g_yh[cur]   :
        (in_sel==1) ? g_tmph      :
        (in_sel==2) ? g_yh[cur^1] : g_hh;
    const __half* __restrict__ Wg = g_wh[wsel];
    const float tval = g_ts7[s];

    // ---- loader geometry: 4 slots per thread, slot -> (row 0..127, seg 0..7) ----
    int rowA[4], segA[4], pxn[4], pxh[4], pxw[4];
    #pragma unroll
    for (int j=0;j<4;j++){
        int sl = tid + j*256;
        rowA[j] = sl >> 3; segA[j] = sl & 7;
        int m = blockIdx.x*128 + rowA[j];
        pxn[j] = (m >> 10) << 10;
        pxh[j] = (m >> 5) & 31;
        pxw[j] = m & 31;
    }

    // ---- compute geometry: warp (wid&3)->m0, (wid>>2)->n0 ----
    const int m0 = (wid & 3) * 32;
    const int n0 = (wid >> 2) * 64;
    const uint32_t aoffbase = (uint32_t)((m0 + (lane & 15))*ROWB + ((lane >> 4)*8)*2);
    const uint32_t boffbase = (uint32_t)((n0 + (lane & 7) + ((lane >> 4) << 3))*ROWB + (((lane >> 3) & 1)*8)*2);

    float acc[2][8][4];
    #pragma unroll
    for (int i=0;i<2;i++)
        #pragma unroll
        for (int j=0;j<8;j++)
            #pragma unroll
            for (int q=0;q<4;q++) acc[i][j][q]=0.f;

    // ---- chunk loader: chunk c -> tap = c>>1, ci0 = (c&1)*64 ----
    auto load_chunk = [&](int c, int st){
        int tap = c >> 1, ci0 = (c & 1) << 6;
        int dh = tap/3 - 1, dw = tap - (tap/3)*3 - 1;
        uint32_t base = sb + st*STG;
        int wbase = tap*16384 + ci0;
        #pragma unroll
        for (int j=0;j<4;j++){
            int row = rowA[j], seg = segA[j];
            uint32_t dA = base + (uint32_t)(row*ROWB + seg*16);
            int hs = pxh[j] + dh, ws = pxw[j] + dw;
            bool v = ((unsigned)hs < 32u) && ((unsigned)ws < 32u);
            long off = v ? (((long)(pxn[j] + hs*32 + ws)) << 7) + ci0 + seg*8 : 0;
            cpa16(dA + A_OFF, X + off, v ? 16u : 0u);
            cpa16(dA + W_OFF, Wg + (wbase + row*128 + seg*8), 16u);
        }
    };

    load_chunk(0, 0);
    CP_COMMIT();

    #pragma unroll 1
    for (int c=0; c<18; ++c){
        const int st = c & 1;
        if (c < 17){
            load_chunk(c+1, st^1);
            CP_COMMIT();
            CP_WAIT1();
        } else {
            CP_WAIT0();
        }
        __syncthreads();

        const uint32_t cb = sb + st*STG;
        const uint32_t aoff = cb + A_OFF + aoffbase;
        const uint32_t boff = cb + W_OFF + boffbase;
        #pragma unroll
        for (int k16=0; k16<4; ++k16){
            const uint32_t kbyte = (uint32_t)(k16*32);
            uint32_t a0[4], a1[4];
            ldm4(a0, aoff + kbyte);
            ldm4(a1, aoff + 16*ROWB + kbyte);
            #pragma unroll
            for (int j=0;j<4;j++){
                uint32_t b[4];
                ldm4(b, boff + (uint32_t)(j*16*ROWB) + kbyte);
                mma16816(acc[0][2*j],   a0, b[0], b[1]);
                mma16816(acc[0][2*j+1], a0, b[2], b[3]);
                mma16816(acc[1][2*j],   a1, b[0], b[1]);
                mma16816(acc[1][2*j+1], a1, b[2], b[3]);
            }
        }
        __syncthreads();
    }

    // ---- epilogue: + t-channel + bias, relu, store ----
    const int gID = lane >> 2, tq = lane & 3;
    #pragma unroll
    for (int mf=0; mf<2; ++mf){
        #pragma unroll
        for (int rr=0; rr<2; ++rr){
            int r = m0 + mf*16 + rr*8 + gID;
            int m = blockIdx.x*128 + r;
            int hp = (m >> 5) & 31, wp = m & 31;
            int cat = ((hp==0)?0:(hp==31)?6:3) + ((wp==0)?0:(wp==31)?2:1);
            const float* tw = g_tw[wsel][cat];
            #pragma unroll
            for (int nf=0; nf<8; ++nf){
                int col = n0 + nf*8 + tq*2;
                float v0 = fmaxf(acc[mf][nf][rr*2+0] + tval*tw[col]   + Bias[col],   0.f);
                float v1 = fmaxf(acc[mf][nf][rr*2+1] + tval*tw[col+1] + Bias[col+1], 0.f);
                if (out_sel >= 0){
                    *(float2*)(g_k[out_sel] + m*128 + col) = make_float2(v0, v1);
                } else {
                    *(uint32_t*)(g_hh + m*128 + col) = pk2h(__float2half(v0), __float2half(v1));
                }
            }
        }
    }
}

// ============ launch ============
extern "C" void kernel_launch(void* const* d_in, const int* in_sizes, int n_in,
                              void* d_out, int out_size){
    const float* x = 0; const float* w[2] = {0,0}; const float* b[2] = {0,0};
    int nw=0, nb_=0;
    for (int i=0;i<n_in;i++){
        if (in_sizes[i] == NTOT) x = (const float*)d_in[i];
        else if (in_sizes[i] == WSIZE){ if (nw<2) w[nw++] = (const float*)d_in[i]; }
        else if (in_sizes[i] == CH){ if (nb_<2) b[nb_++] = (const float*)d_in[i]; }
    }
    const float* w1=w[0]; const float* b1=b[0];
    const float* w2=w[1]; const float* b2=b[1];
    float* out = (float*)d_out;

    cudaFuncSetAttribute(k_conv, cudaFuncAttributeMaxDynamicSharedMemorySize, CONV_SMEM);

    k_prep_w<<<(2*NWB + 255)/256, 256>>>(w1, w2);
    k_prep_tw<<<1, 256>>>(w1, w2);
    k_init<<<EW_BLOCKS, 256>>>(x);

    for (int it=0; it<MAX_STEPS; ++it){
        for (int s=0;s<7;++s){
            if (s > 0) k_combine<<<EW_BLOCKS,256>>>(s);
            int in1 = (s==0) ? 0 : ((s==6) ? 2 : 1);
            k_conv<<<256,256,CONV_SMEM>>>(b1, 0, s, in1, -1);  // h = relu(conv1(cat(y_s,t))+b1)
            k_conv<<<256,256,CONV_SMEM>>>(b2, 1, s, 3, s);     // k_s = relu(conv2(cat(h,t))+b2)
        }
        k_err<<<ERR_BLOCKS,256>>>();
        k_reduce_ctl<<<1,256>>>();
    }
    k_final<<<EW_BLOCKS,256>>>(out);
}

// round 6
// speedup vs baseline: 3.8434x; 1.1481x over previous
#include <cuda_runtime.h>
#include <cuda_fp16.h>
#include <stdint.h>
#include <math.h>

#define CH 128
#define NPIX 32768              // 32*32*32
#define NTOT (NPIX*CH)          // 4194304
#define NQ (NTOT/4)
#define WSIZE (3*3*129*128)
#define NWB (9*128*128)         // 147456
#define MAX_STEPS 32
#define GRID 256
#define NTILE 256

// ---- Dormand-Prince coefficients ----
#define C10 0.2f
#define C20 ((float)(3.0/40.0))
#define C21 ((float)(9.0/40.0))
#define C30 ((float)(44.0/45.0))
#define C31 ((float)(-56.0/15.0))
#define C32 ((float)(32.0/9.0))
#define C40 ((float)(19372.0/6561.0))
#define C41 ((float)(-25360.0/2187.0))
#define C42 ((float)(64448.0/6561.0))
#define C43 ((float)(-212.0/729.0))
#define C50 ((float)(9017.0/3168.0))
#define C51 ((float)(-355.0/33.0))
#define C52 ((float)(46732.0/5247.0))
#define C53 ((float)(49.0/176.0))
#define C54 ((float)(-5103.0/18656.0))
#define B0c ((float)(35.0/384.0))
#define B2c ((float)(500.0/1113.0))
#define B3c ((float)(125.0/192.0))
#define B4c ((float)(-2187.0/6784.0))
#define B5c ((float)(11.0/84.0))
#define E0c ((float)(35.0/384.0 - 5179.0/57600.0))
#define E2c ((float)(500.0/1113.0 - 7571.0/16695.0))
#define E3c ((float)(125.0/192.0 - 393.0/640.0))
#define E4c ((float)(-2187.0/6784.0 + 92097.0/339200.0))
#define E5c ((float)(11.0/84.0 - 187.0/2100.0))
#define E6c ((float)(-1.0/40.0))

// ---- Persistent state ----
__device__ __align__(16) float g_yf[2][NTOT];        // ping-pong fp32 y ([cur^1] holds y5)
__device__ __align__(16) float g_k[7][NTOT];
__device__ __align__(16) __half g_yh[2][NTOT];       // fp16 mirrors
__device__ __align__(16) __half g_tmph[NTOT];        // fp16 stage input (incl y5h at s=6)
__device__ __align__(16) __half g_hh[NTOT];
__device__ __align__(16) __half g_wh[2][NWB];        // [conv][tap*16384 + co*128 + ci]
__device__ float g_tw[2][9][128];
__device__ double g_part[NTILE];
__device__ float g_t, g_dt, g_dtc, g_ts7[7];
__device__ int g_done, g_cur;
__device__ unsigned g_arrive, g_gen;                 // grid barrier (zero-init)

// ---- conv smem: 3-stage ring of {A, W}; rows 128 x (64 fp16 = 128B + 16B pad) ----
#define ROWB 144
#define TILE_B (128*ROWB)        // 18432
#define A_OFF 0
#define W_OFF TILE_B
#define STG   (2*TILE_B)         // 36864
#define CONV_SMEM (3*STG)        // 110592

// ============ PTX wrappers (base ISA, valid for compute_103) ============
__device__ __forceinline__ uint32_t smem_u32(const void* p){
    uint32_t a;
    asm("{ .reg .u64 t; cvta.to.shared.u64 t, %1; cvt.u32.u64 %0, t; }" : "=r"(a) : "l"(p));
    return a;
}
__device__ __forceinline__ void cpa16(uint32_t dst, const void* src, uint32_t sz){
    asm volatile("cp.async.cg.shared.global [%0], [%1], 16, %2;" :: "r"(dst), "l"(src), "r"(sz));
}
#define CP_COMMIT() asm volatile("cp.async.commit_group;" ::: "memory")
#define CP_WAIT1()  asm volatile("cp.async.wait_group 1;" ::: "memory")
#define CP_WAIT0()  asm volatile("cp.async.wait_group 0;" ::: "memory")

__device__ __forceinline__ void ldm4(uint32_t* r, uint32_t addr){
    asm volatile("ldmatrix.sync.aligned.m8n8.x4.shared.b16 {%0,%1,%2,%3}, [%4];"
        : "=r"(r[0]), "=r"(r[1]), "=r"(r[2]), "=r"(r[3]) : "r"(addr));
}
__device__ __forceinline__ void mma16816(float* c, const uint32_t* a, uint32_t b0, uint32_t b1){
    asm volatile("mma.sync.aligned.m16n8k16.row.col.f32.f16.f16.f32 "
        "{%0,%1,%2,%3}, {%4,%5,%6,%7}, {%8,%9}, {%0,%1,%2,%3};"
        : "+f"(c[0]), "+f"(c[1]), "+f"(c[2]), "+f"(c[3])
        : "r"(a[0]), "r"(a[1]), "r"(a[2]), "r"(a[3]), "r"(b0), "r"(b1));
}
__device__ __forceinline__ uint32_t pk2h(__half a, __half b){
    return (uint32_t)__half_as_ushort(a) | ((uint32_t)__half_as_ushort(b) << 16);
}
__device__ __forceinline__ void h_store4(__half* Hp, int e, float4 v){
    uint2 H = make_uint2(pk2h(__float2half(v.x), __float2half(v.y)),
                         pk2h(__float2half(v.z), __float2half(v.w)));
    *(uint2*)(Hp + e) = H;
}

// ---- grid-wide sense barrier (all GRID CTAs resident) ----
__device__ __forceinline__ void gsync(){
    __threadfence();
    __syncthreads();
    if (threadIdx.x == 0){
        unsigned g;
        asm volatile("ld.acquire.gpu.u32 %0, [%1];" : "=r"(g) : "l"(&g_gen));
        unsigned old;
        asm volatile("atom.add.release.gpu.u32 %0, [%1], 1;" : "=r"(old) : "l"(&g_arrive) : "memory");
        if (old == GRID-1){
            asm volatile("st.relaxed.gpu.u32 [%0], 0;" :: "l"(&g_arrive) : "memory");
            asm volatile("st.release.gpu.u32 [%0], %1;" :: "l"(&g_gen), "r"(g+1) : "memory");
        } else {
            unsigned cur;
            do {
                __nanosleep(64);
                asm volatile("ld.acquire.gpu.u32 %0, [%1];" : "=r"(cur) : "l"(&g_gen));
            } while (cur == g);
        }
    }
    __syncthreads();
}

#define LDK(j) __ldcg((const float2*)(g_k[j]+idx))

// ============ conv phase (runs on every CTA; tile == blockIdx.x) ============
__device__ __forceinline__ void conv_phase(
    uint32_t sb, int tile, int wsel, int s,
    const float* __restrict__ Bias, float dtc, float tval, int cur,
    double* sdErr)
{
    const int tid  = threadIdx.x;
    const int wid  = tid >> 5;
    const int lane = tid & 31;

    const __half* __restrict__ X = (wsel==0) ? ((s==0) ? g_yh[cur] : g_tmph) : g_hh;
    const __half* __restrict__ Wg = g_wh[wsel];

    // loader geometry: 4 slots/thread -> (row 0..127, seg 0..7)
    int rowA[4], segA[4], pxn[4], pxh[4], pxw[4];
    #pragma unroll
    for (int j=0;j<4;j++){
        int sl = tid + j*256;
        rowA[j] = sl >> 3; segA[j] = sl & 7;
        int m = tile*128 + rowA[j];
        pxn[j] = (m >> 10) << 10;
        pxh[j] = (m >> 5) & 31;
        pxw[j] = m & 31;
    }
    const int m0 = (wid & 3) * 32;
    const int n0 = (wid >> 2) * 64;
    const uint32_t aoffbase = (uint32_t)((m0 + (lane & 15))*ROWB + ((lane >> 4)*8)*2);
    const uint32_t boffbase = (uint32_t)((n0 + (lane & 7) + ((lane >> 4) << 3))*ROWB + (((lane >> 3) & 1)*8)*2);

    float acc[2][8][4];
    #pragma unroll
    for (int i=0;i<2;i++)
        #pragma unroll
        for (int j=0;j<8;j++)
            #pragma unroll
            for (int q=0;q<4;q++) acc[i][j][q]=0.f;

    auto load_chunk = [&](int c, int st){
        int tap = c >> 1, ci0 = (c & 1) << 6;
        int dh = tap/3 - 1, dw = tap - (tap/3)*3 - 1;
        uint32_t base = sb + st*STG;
        int wbase = tap*16384 + ci0;
        #pragma unroll
        for (int j=0;j<4;j++){
            uint32_t dA = base + (uint32_t)(rowA[j]*ROWB + segA[j]*16);
            int hs = pxh[j] + dh, ws = pxw[j] + dw;
            bool v = ((unsigned)hs < 32u) && ((unsigned)ws < 32u);
            long off = v ? (((long)(pxn[j] + hs*32 + ws)) << 7) + ci0 + segA[j]*8 : 0;
            cpa16(dA + A_OFF, X + off, v ? 16u : 0u);
            cpa16(dA + W_OFF, Wg + (wbase + rowA[j]*128 + segA[j]*8), 16u);
        }
    };

    load_chunk(0,0); CP_COMMIT();
    load_chunk(1,1); CP_COMMIT();

    #pragma unroll 1
    for (int c=0; c<18; ++c){
        if (c==17) CP_WAIT0(); else CP_WAIT1();
        __syncthreads();
        if (c<16){ load_chunk(c+2, (c+2)%3); CP_COMMIT(); }

        const uint32_t cb = sb + (c%3)*STG;
        const uint32_t aoff = cb + A_OFF + aoffbase;
        const uint32_t boff = cb + W_OFF + boffbase;
        #pragma unroll
        for (int k16=0; k16<4; ++k16){
            const uint32_t kb = (uint32_t)(k16*32);
            uint32_t a0[4], a1[4];
            ldm4(a0, aoff + kb);
            ldm4(a1, aoff + 16*ROWB + kb);
            #pragma unroll
            for (int j=0;j<4;j++){
                uint32_t b[4];
                ldm4(b, boff + (uint32_t)(j*16*ROWB) + kb);
                mma16816(acc[0][2*j],   a0, b[0], b[1]);
                mma16816(acc[0][2*j+1], a0, b[2], b[3]);
                mma16816(acc[1][2*j],   a1, b[0], b[1]);
                mma16816(acc[1][2*j+1], a1, b[2], b[3]);
            }
        }
    }

    // ---- epilogue: + t-channel + bias, relu, store (+ fused combine / y5 / err) ----
    const int gID = lane >> 2, tq = lane & 3;
    double errsum = 0.0;
    #pragma unroll
    for (int mf=0; mf<2; ++mf){
        #pragma unroll
        for (int rr=0; rr<2; ++rr){
            int r = m0 + mf*16 + rr*8 + gID;
            int m = tile*128 + r;
            int hp = (m >> 5) & 31, wp = m & 31;
            int cat = ((hp==0)?0:(hp==31)?6:3) + ((wp==0)?0:(wp==31)?2:1);
            const float* tw = g_tw[wsel][cat];
            #pragma unroll
            for (int nf=0; nf<8; ++nf){
                int col = n0 + nf*8 + tq*2;
                float v0 = fmaxf(acc[mf][nf][rr*2+0] + tval*tw[col]   + Bias[col],   0.f);
                float v1 = fmaxf(acc[mf][nf][rr*2+1] + tval*tw[col+1] + Bias[col+1], 0.f);
                int idx = m*128 + col;
                if (wsel==0){
                    *(uint32_t*)(g_hh + idx) = pk2h(__float2half(v0), __float2half(v1));
                } else {
                    *(float2*)(g_k[s] + idx) = make_float2(v0, v1);
                    if (s <= 5){
                        float2 y = __ldcg((const float2*)(g_yf[cur] + idx));
                        float c0, c1;
                        if (s==0){ c0 = C10*v0; c1 = C10*v1; }
                        else if (s==1){
                            float2 k0=LDK(0);
                            c0 = C20*k0.x + C21*v0; c1 = C20*k0.y + C21*v1;
                        } else if (s==2){
                            float2 k0=LDK(0), k1=LDK(1);
                            c0 = C30*k0.x + C31*k1.x + C32*v0;
                            c1 = C30*k0.y + C31*k1.y + C32*v1;
                        } else if (s==3){
                            float2 k0=LDK(0), k1=LDK(1), k2=LDK(2);
                            c0 = C40*k0.x + C41*k1.x + C42*k2.x + C43*v0;
                            c1 = C40*k0.y + C41*k1.y + C42*k2.y + C43*v1;
                        } else if (s==4){
                            float2 k0=LDK(0), k1=LDK(1), k2=LDK(2), k3=LDK(3);
                            c0 = C50*k0.x + C51*k1.x + C52*k2.x + C53*k3.x + C54*v0;
                            c1 = C50*k0.y + C51*k1.y + C52*k2.y + C53*k3.y + C54*v1;
                        } else {
                            float2 k0=LDK(0), k2=LDK(2), k3=LDK(3), k4=LDK(4);
                            c0 = B0c*k0.x + B2c*k2.x + B3c*k3.x + B4c*k4.x + B5c*v0;
                            c1 = B0c*k0.y + B2c*k2.y + B3c*k3.y + B4c*k4.y + B5c*v1;
                        }
                        float t0 = y.x + dtc*c0, t1 = y.y + dtc*c1;
                        uint32_t pk = pk2h(__float2half(t0), __float2half(t1));
                        *(uint32_t*)(g_tmph + idx) = pk;
                        if (s==5){
                            // y5: fp32 for error/commit + fp16 mirror for next step's stage 0
                            *(float2*)(g_yf[cur^1] + idx) = make_float2(t0, t1);
                            *(uint32_t*)(g_yh[cur^1] + idx) = pk;
                        }
                    } else {
                        float2 k0=LDK(0), k2=LDK(2), k3=LDK(3), k4=LDK(4), k5=LDK(5);
                        float2 y  = __ldcg((const float2*)(g_yf[cur]   + idx));
                        float2 y5 = __ldcg((const float2*)(g_yf[cur^1] + idx));
                        float e0 = dtc*(E0c*k0.x + E2c*k2.x + E3c*k3.x + E4c*k4.x + E5c*k5.x + E6c*v0);
                        float e1 = dtc*(E0c*k0.y + E2c*k2.y + E3c*k3.y + E4c*k4.y + E5c*k5.y + E6c*v1);
                        float sc0 = 1e-3f + 1e-3f*fmaxf(fabsf(y.x), fabsf(y5.x));
                        float sc1 = 1e-3f + 1e-3f*fmaxf(fabsf(y.y), fabsf(y5.y));
                        float r0 = e0/sc0, r1 = e1/sc1;
                        errsum += (double)r0*(double)r0 + (double)r1*(double)r1;
                    }
                }
            }
        }
    }
    if (wsel==1 && s==6){
        sdErr[tid] = errsum;
        __syncthreads();
        for (int o=128; o>0; o>>=1){
            if (tid < o) sdErr[tid] += sdErr[tid+o];
            __syncthreads();
        }
        if (tid==0) g_part[tile] = sdErr[0];
    }
}

// ============ the single persistent kernel ============
__global__ __launch_bounds__(256,2)
void k_solver(const float* __restrict__ x,
              const float* __restrict__ w1, const float* __restrict__ b1,
              const float* __restrict__ w2, const float* __restrict__ b2,
              float* __restrict__ out)
{
    extern __shared__ __align__(16) char dsm[];
    __shared__ double sd[256];
    const uint32_t sb = smem_u32(dsm);
    const int bid = blockIdx.x, tid = threadIdx.x;
    const int gt = bid*256 + tid;
    const int gstride = GRID*256;

    // ---- prep: weights (transposed fp16) ----
    for (int i=gt; i<2*NWB; i+=gstride){
        int conv = i / NWB, r = i % NWB;
        int tap = r >> 14, co = (r >> 7) & 127, ci = r & 127;
        float v = (conv ? w2 : w1)[(tap*129 + ci)*128 + co];
        g_wh[conv][r] = __float2half(v);
    }
    // ---- prep: t-channel weight sums per border category ----
    if (bid==0){
        int conv = tid >> 7, co = tid & 127;
        const float* w = conv ? w2 : w1;
        for (int cat=0; cat<9; cat++){
            int hc = cat/3, wc = cat%3;
            float ssum = 0.f;
            for (int tap=0; tap<9; tap++){
                int dh = tap/3 - 1, dw = tap%3 - 1;
                bool okh = !((hc==0 && dh<0) || (hc==2 && dh>0));
                bool okw = !((wc==0 && dw<0) || (wc==2 && dw>0));
                if (okh && okw) ssum += w[(tap*129 + 128)*128 + co];
            }
            g_tw[conv][cat][co] = ssum;
        }
    }
    // ---- init y ----
    for (int q=gt; q<NQ; q+=gstride){
        float4 v = ((const float4*)x)[q];
        ((float4*)g_yf[0])[q] = v;
        h_store4(g_yh[0], q*4, v);
    }
    if (gt==0){
        g_t=0.f; g_dt=0.05f; g_done=0; g_cur=0;
        float dtc = 0.05f;
        g_dtc = dtc;
        g_ts7[0]=0.f;      g_ts7[1]=0.2f*dtc; g_ts7[2]=0.3f*dtc;
        g_ts7[3]=0.8f*dtc; g_ts7[4]=((float)(8.0/9.0))*dtc;
        g_ts7[5]=dtc;      g_ts7[6]=dtc;
    }
    gsync();

    // ---- solver loop ----
    for (int it=0; it<MAX_STEPS; ++it){
        if (__ldcg(&g_done)) break;
        const float dtc = __ldcg(&g_dtc);
        const int cur = __ldcg(&g_cur);
        for (int s=0; s<7; ++s){
            const float tval = __ldcg(&g_ts7[s]);
            conv_phase(sb, bid, 0, s, b1, dtc, tval, cur, sd);   // h
            gsync();
            conv_phase(sb, bid, 1, s, b2, dtc, tval, cur, sd);   // k_s (+fused)
            gsync();
        }
        // ---- controller (CTA 0) ----
        if (bid==0){
            double v=0.0;
            for (int i=tid; i<NTILE; i+=256) v += __ldcg(&g_part[i]);
            sd[tid]=v; __syncthreads();
            for (int o=128; o>0; o>>=1){ if (tid<o) sd[tid]+=sd[tid+o]; __syncthreads(); }
            if (tid==0){
                float err_norm = sqrtf((float)(sd[0] / (double)NTOT));
                err_norm = fmaxf(err_norm, 1e-10f);
                int accept = (err_norm <= 1.0f) ? 1 : 0;
                float factor = 0.9f * powf(err_norm, -0.2f);
                factor = fminf(fmaxf(factor, 0.2f), 10.0f);
                float t = __ldcg(&g_t), dtcv = __ldcg(&g_dtc);
                if (accept){ t += dtcv; g_cur = cur^1; }
                float dt = dtcv * factor;
                g_t = t; g_dt = dt;
                if (t >= 1.0f - 1e-6f){ g_done = 1; }
                else {
                    float d2 = fminf(dt, 1.0f - t);
                    g_dtc = d2;
                    g_ts7[0]=t;         g_ts7[1]=t+0.2f*d2; g_ts7[2]=t+0.3f*d2;
                    g_ts7[3]=t+0.8f*d2; g_ts7[4]=t+((float)(8.0/9.0))*d2;
                    g_ts7[5]=t+d2;      g_ts7[6]=t+d2;
                }
            }
        }
        gsync();
    }

    // ---- final copy ----
    const int cur = __ldcg(&g_cur);
    for (int q=gt; q<NQ; q+=gstride)
        ((float4*)out)[q] = __ldcg((const float4*)g_yf[cur] + q);
}

// ============ launch ============
extern "C" void kernel_launch(void* const* d_in, const int* in_sizes, int n_in,
                              void* d_out, int out_size){
    const float* x = 0; const float* w[2] = {0,0}; const float* b[2] = {0,0};
    int nw=0, nb_=0;
    for (int i=0;i<n_in;i++){
        if (in_sizes[i] == NTOT) x = (const float*)d_in[i];
        else if (in_sizes[i] == WSIZE){ if (nw<2) w[nw++] = (const float*)d_in[i]; }
        else if (in_sizes[i] == CH){ if (nb_<2) b[nb_++] = (const float*)d_in[i]; }
    }
    cudaFuncSetAttribute(k_solver, cudaFuncAttributeMaxDynamicSharedMemorySize, CONV_SMEM);
    cudaFuncSetAttribute(k_solver, cudaFuncAttributePreferredSharedMemoryCarveout, 100);
    k_solver<<<GRID, 256, CONV_SMEM>>>(x, w[0], b[0], w[1], b[1], (float*)d_out);
}